// round 2
// baseline (speedup 1.0000x reference)
#include <cuda_runtime.h>
#include <cuda_bf16.h>
#include <cstddef>

// ---------------------------------------------------------------------------
// SNN forward, fp32 with packed f32x2 FMA (fma.rn.f32x2).
// Layouts: all activations/states stored feature-major: X[k][b], b contiguous
// (128 floats per row) so warps load coalesced 16B per lane (4 batch rows).
// ---------------------------------------------------------------------------

#define B    128
#define T    100
#define DIN  700
#define H    1024
#define O    20
#define SCALE 0.09999950000374997f   // 0.1 / sqrt(1 + 1e-5)

typedef unsigned long long ull;

// ---- device scratch ----
__device__ float g_XT[T * DIN * B];          // [t][i][b]
__device__ float g_state[12 * H * B];        // [parity][6][H*B]: mem1,spk1,bb1,mem2,spk2,bb2
__device__ float g_m3[2 * O * B];            // [parity][O*B]
__device__ float g_d1[H * B];
__device__ float g_d2[H * B];
__device__ float g_d3[O * B];

enum { MEM1 = 0, SPK1, BB1, MEM2, SPK2, BB2 };

// ---- packed f32x2 helpers ----
__device__ __forceinline__ void fma2(ull& d, ull a, ull b) {
    asm("fma.rn.f32x2 %0, %1, %2, %0;" : "+l"(d) : "l"(a), "l"(b));
}
__device__ __forceinline__ ull dup2(float w) {
    ull r; asm("mov.b64 %0, {%1, %1};" : "=l"(r) : "f"(w)); return r;
}
__device__ __forceinline__ float2 unp2(ull v) {
    float2 r; asm("mov.b64 {%0, %1}, %2;" : "=f"(r.x), "=f"(r.y) : "l"(v)); return r;
}
__device__ __forceinline__ float sigmf(float x) { return 1.0f / (1.0f + expf(-x)); }

// ---- GEMM inner phases (warp-per-neuron, lane = 4 batch rows) ----
// acc over K of A[k][b] * Wrow[k], A row stride = 128 floats = 512 bytes.
__device__ __forceinline__ void gemm_phase(ull& aL, ull& aH,
                                           const float* __restrict__ A,
                                           const float* __restrict__ Wrow,
                                           int K, int lane) {
    const char* a = (const char*)(A + (lane << 2));
    #pragma unroll 2
    for (int k = 0; k < K; k += 4) {
        float4 w4 = *(const float4*)(Wrow + k);
        ulonglong2 v0 = *(const ulonglong2*)(a);
        ulonglong2 v1 = *(const ulonglong2*)(a + 512);
        ulonglong2 v2 = *(const ulonglong2*)(a + 1024);
        ulonglong2 v3 = *(const ulonglong2*)(a + 1536);
        ull w0 = dup2(w4.x), w1 = dup2(w4.y), w2 = dup2(w4.z), w3 = dup2(w4.w);
        fma2(aL, v0.x, w0); fma2(aH, v0.y, w0);
        fma2(aL, v1.x, w1); fma2(aH, v1.y, w1);
        fma2(aL, v2.x, w2); fma2(aH, v2.y, w2);
        fma2(aL, v3.x, w3); fma2(aH, v3.y, w3);
        a += 2048;
    }
}

// Two accumulators sharing the same A rows (tauM & tauA dense-input phase).
__device__ __forceinline__ void gemm_phase_dual(ull& mL, ull& mH, ull& aL, ull& aH,
                                                const float* __restrict__ A,
                                                const float* __restrict__ Wm,
                                                const float* __restrict__ Wa,
                                                int K, int lane) {
    const char* a = (const char*)(A + (lane << 2));
    #pragma unroll 2
    for (int k = 0; k < K; k += 4) {
        float4 wm4 = *(const float4*)(Wm + k);
        float4 wa4 = *(const float4*)(Wa + k);
        ulonglong2 v0 = *(const ulonglong2*)(a);
        ulonglong2 v1 = *(const ulonglong2*)(a + 512);
        ulonglong2 v2 = *(const ulonglong2*)(a + 1024);
        ulonglong2 v3 = *(const ulonglong2*)(a + 1536);
        ull m0 = dup2(wm4.x), m1 = dup2(wm4.y), m2 = dup2(wm4.z), m3 = dup2(wm4.w);
        ull q0 = dup2(wa4.x), q1 = dup2(wa4.y), q2 = dup2(wa4.z), q3 = dup2(wa4.w);
        fma2(mL, v0.x, m0); fma2(mH, v0.y, m0); fma2(aL, v0.x, q0); fma2(aH, v0.y, q0);
        fma2(mL, v1.x, m1); fma2(mH, v1.y, m1); fma2(aL, v1.x, q1); fma2(aH, v1.y, q1);
        fma2(mL, v2.x, m2); fma2(mH, v2.y, m2); fma2(aL, v2.x, q2); fma2(aH, v2.y, q2);
        fma2(mL, v3.x, m3); fma2(mH, v3.y, m3); fma2(aL, v3.x, q3); fma2(aH, v3.y, q3);
        a += 2048;
    }
}

// Two accumulators, two DIFFERENT A matrices (mem phase for tauM, bb phase for tauA).
__device__ __forceinline__ void gemm_phase_split(ull& mL, ull& mH, ull& aL, ull& aH,
                                                 const float* __restrict__ Am,
                                                 const float* __restrict__ Ab,
                                                 const float* __restrict__ Wm,
                                                 const float* __restrict__ Wa,
                                                 int K, int lane) {
    const char* am = (const char*)(Am + (lane << 2));
    const char* ab = (const char*)(Ab + (lane << 2));
    #pragma unroll 2
    for (int k = 0; k < K; k += 4) {
        float4 wm4 = *(const float4*)(Wm + k);
        float4 wa4 = *(const float4*)(Wa + k);
        ulonglong2 u0 = *(const ulonglong2*)(am);
        ulonglong2 u1 = *(const ulonglong2*)(am + 512);
        ulonglong2 u2 = *(const ulonglong2*)(am + 1024);
        ulonglong2 u3 = *(const ulonglong2*)(am + 1536);
        ulonglong2 v0 = *(const ulonglong2*)(ab);
        ulonglong2 v1 = *(const ulonglong2*)(ab + 512);
        ulonglong2 v2 = *(const ulonglong2*)(ab + 1024);
        ulonglong2 v3 = *(const ulonglong2*)(ab + 1536);
        ull m0 = dup2(wm4.x), m1 = dup2(wm4.y), m2 = dup2(wm4.z), m3 = dup2(wm4.w);
        ull q0 = dup2(wa4.x), q1 = dup2(wa4.y), q2 = dup2(wa4.z), q3 = dup2(wa4.w);
        fma2(mL, u0.x, m0); fma2(mH, u0.y, m0); fma2(aL, v0.x, q0); fma2(aH, v0.y, q0);
        fma2(mL, u1.x, m1); fma2(mH, u1.y, m1); fma2(aL, v1.x, q1); fma2(aH, v1.y, q1);
        fma2(mL, u2.x, m2); fma2(mH, u2.y, m2); fma2(aL, v2.x, q2); fma2(aH, v2.y, q2);
        fma2(mL, u3.x, m3); fma2(mH, u3.y, m3); fma2(aL, v3.x, q3); fma2(aH, v3.y, q3);
        am += 2048; ab += 2048;
    }
}

// ---------------------------------------------------------------------------
// K1: dense layer: D[o][b] = scale*(A1·W1[o] + A2·W2[o] + b1[o] + b2[o])
// grid = 128 blocks * 8 warps = 1024 neurons; lane handles 4 batch rows.
// ---------------------------------------------------------------------------
__global__ __launch_bounds__(256) void dense_k(
    const float* __restrict__ A1, const float* __restrict__ W1, int K1,
    const float* __restrict__ A2, const float* __restrict__ W2, int K2,
    const float* __restrict__ bias1, const float* __restrict__ bias2,
    float* __restrict__ D)
{
    const int warp = threadIdx.x >> 5, lane = threadIdx.x & 31;
    const int o = (blockIdx.x << 3) + warp;
    ull aL = 0ull, aH = 0ull;
    gemm_phase(aL, aH, A1, W1 + (size_t)o * K1, K1, lane);
    gemm_phase(aL, aH, A2, W2 + (size_t)o * K2, K2, lane);
    float2 lo = unp2(aL), hi = unp2(aH);
    float bb = bias1[o] + bias2[o];
    float4 r;
    r.x = SCALE * (lo.x + bb);
    r.y = SCALE * (lo.y + bb);
    r.z = SCALE * (hi.x + bb);
    r.w = SCALE * (hi.y + bb);
    *(float4*)(D + o * B + (lane << 2)) = r;
}

// ---------------------------------------------------------------------------
// K2: fused tauM/tauA GEMMs (K=2048 each, split weights) + adaptive mem update.
//   tm = sigmoid(D·Wm[:, :H] + mem·Wm[:, H:] + bm)
//   ta = sigmoid(D·Wa[:, :H] + bb ·Wa[:, H:] + ba)
//   b' = ta*b + (1-ta)*spk ; Bth = 0.1 + 1.8*b' ; m' = m + (D-m)*tm
//   spk' = (m' > Bth) ; m'' = (1-spk')*m'
// ---------------------------------------------------------------------------
__global__ __launch_bounds__(256) void tau_update_k(
    const float* __restrict__ Dn, const float* __restrict__ MemOld,
    const float* __restrict__ BbOld, const float* __restrict__ SpkOld,
    const float* __restrict__ Wm, const float* __restrict__ Wa,
    const float* __restrict__ bm, const float* __restrict__ ba,
    float* __restrict__ MemNew, float* __restrict__ SpkNew, float* __restrict__ BbNew)
{
    const int warp = threadIdx.x >> 5, lane = threadIdx.x & 31;
    const int o = (blockIdx.x << 3) + warp;
    const float* wm = Wm + (size_t)o * (2 * H);
    const float* wa = Wa + (size_t)o * (2 * H);
    ull mL = 0ull, mH = 0ull, aL = 0ull, aH = 0ull;
    gemm_phase_dual (mL, mH, aL, aH, Dn, wm, wa, H, lane);
    gemm_phase_split(mL, mH, aL, aH, MemOld, BbOld, wm + H, wa + H, H, lane);

    const int idx = o * B + (lane << 2);
    float4 dn = *(const float4*)(Dn + idx);
    float4 me = *(const float4*)(MemOld + idx);
    float4 bo = *(const float4*)(BbOld + idx);
    float4 sp = *(const float4*)(SpkOld + idx);
    float bmo = bm[o], bao = ba[o];
    float2 m01 = unp2(mL), m23 = unp2(mH), a01 = unp2(aL), a23 = unp2(aH);

    float tmv[4] = { sigmf(m01.x + bmo), sigmf(m01.y + bmo), sigmf(m23.x + bmo), sigmf(m23.y + bmo) };
    float tav[4] = { sigmf(a01.x + bao), sigmf(a01.y + bao), sigmf(a23.x + bao), sigmf(a23.y + bao) };
    float dv[4]  = { dn.x, dn.y, dn.z, dn.w };
    float mv[4]  = { me.x, me.y, me.z, me.w };
    float bv[4]  = { bo.x, bo.y, bo.z, bo.w };
    float sv[4]  = { sp.x, sp.y, sp.z, sp.w };

    float nm[4], ns[4], nb[4];
    #pragma unroll
    for (int j = 0; j < 4; j++) {
        float bn  = tav[j] * bv[j] + (1.0f - tav[j]) * sv[j];
        float Bth = 0.1f + 1.8f * bn;
        float mn  = mv[j] + (dv[j] - mv[j]) * tmv[j];
        float s   = (mn - Bth) > 0.0f ? 1.0f : 0.0f;
        nm[j] = (1.0f - s) * mn;
        ns[j] = s;
        nb[j] = bn;
    }
    *(float4*)(MemNew + idx) = make_float4(nm[0], nm[1], nm[2], nm[3]);
    *(float4*)(SpkNew + idx) = make_float4(ns[0], ns[1], ns[2], ns[3]);
    *(float4*)(BbNew  + idx) = make_float4(nb[0], nb[1], nb[2], nb[3]);
}

// ---------------------------------------------------------------------------
// K3a: D3[o][b] = SCALE*(spk2·w3x[o] + b3x[o]); grid = 20 blocks (one per o),
// 8 warps split K=1024, smem reduction.
// ---------------------------------------------------------------------------
__global__ __launch_bounds__(256) void out_gemm_k(
    const float* __restrict__ Spk2, const float* __restrict__ W3x,
    const float* __restrict__ b3x, float* __restrict__ D3)
{
    __shared__ float red[8][B];
    const int warp = threadIdx.x >> 5, lane = threadIdx.x & 31;
    const int o = blockIdx.x;
    ull aL = 0ull, aH = 0ull;
    gemm_phase(aL, aH, Spk2 + warp * 128 * B, W3x + (size_t)o * H + warp * 128, 128, lane);
    float2 lo = unp2(aL), hi = unp2(aH);
    red[warp][(lane << 2) + 0] = lo.x;
    red[warp][(lane << 2) + 1] = lo.y;
    red[warp][(lane << 2) + 2] = hi.x;
    red[warp][(lane << 2) + 3] = hi.y;
    __syncthreads();
    if (threadIdx.x < B) {
        float s = 0.0f;
        #pragma unroll
        for (int w = 0; w < 8; w++) s += red[w][threadIdx.x];
        D3[o * B + threadIdx.x] = SCALE * (s + b3x[o]);
    }
}

// ---------------------------------------------------------------------------
// K3b: tauM3 (K=40), nmem3 blend, log_softmax over 20 classes. 1 block, 128 thr.
// ---------------------------------------------------------------------------
__global__ __launch_bounds__(128) void out_final_k(
    const float* __restrict__ D3, const float* __restrict__ Mem3Old,
    const float* __restrict__ W3m, const float* __restrict__ b3m,
    float* __restrict__ Mem3New, float* __restrict__ outs)
{
    const int b = threadIdx.x;
    float d3v[O], m3v[O], nm[O];
    #pragma unroll
    for (int k = 0; k < O; k++) { d3v[k] = D3[k * B + b]; m3v[k] = Mem3Old[k * B + b]; }
    #pragma unroll
    for (int o = 0; o < O; o++) {
        const float* w = W3m + o * (2 * O);
        float acc = b3m[o];
        #pragma unroll
        for (int k = 0; k < O; k++) acc += d3v[k] * w[k];
        #pragma unroll
        for (int k = 0; k < O; k++) acc += m3v[k] * w[O + k];
        float tm = sigmf(acc);
        float v = (1.0f - tm) * m3v[o] + d3v[o] * tm;
        nm[o] = v;
        Mem3New[o * B + b] = v;
    }
    float mx = nm[0];
    #pragma unroll
    for (int o = 1; o < O; o++) mx = fmaxf(mx, nm[o]);
    float s = 0.0f;
    #pragma unroll
    for (int o = 0; o < O; o++) s += expf(nm[o] - mx);
    float lse = logf(s);
    #pragma unroll
    for (int o = 0; o < O; o++) outs[b * O + o] = nm[o] - mx - lse;
}

// ---------------------------------------------------------------------------
// Transposes
// ---------------------------------------------------------------------------
// inputs [B][T][DIN] -> XT[t][i][b]
__global__ void transpose_x_k(const float* __restrict__ in, float* __restrict__ out)
{
    __shared__ float tile[32][33];
    const int t = blockIdx.z;
    const int i0 = blockIdx.x * 32, b0 = blockIdx.y * 32;
    for (int r = threadIdx.y; r < 32; r += 8) {
        int bb = b0 + r, i = i0 + threadIdx.x;
        tile[r][threadIdx.x] = (i < DIN) ? in[(size_t)bb * T * DIN + (size_t)t * DIN + i] : 0.0f;
    }
    __syncthreads();
    for (int r = threadIdx.y; r < 32; r += 8) {
        int i = i0 + r, bb = b0 + threadIdx.x;
        if (i < DIN) out[((size_t)t * DIN + i) * B + bb] = tile[threadIdx.x][r];
    }
}

// in [B][F] -> st[j*B + b]
__global__ void tr_in_k(const float* __restrict__ in, float* __restrict__ st, int F)
{
    __shared__ float tile[32][33];
    const int j0 = blockIdx.x * 32, b0 = blockIdx.y * 32;
    for (int r = threadIdx.y; r < 32; r += 8) {
        int bb = b0 + r, j = j0 + threadIdx.x;
        tile[r][threadIdx.x] = (j < F) ? in[(size_t)bb * F + j] : 0.0f;
    }
    __syncthreads();
    for (int r = threadIdx.y; r < 32; r += 8) {
        int j = j0 + r, bb = b0 + threadIdx.x;
        if (j < F) st[(size_t)j * B + bb] = tile[threadIdx.x][r];
    }
}

// st[j*B + b] -> out[b*F + j]
__global__ void tr_out_k(const float* __restrict__ st, float* __restrict__ out, int F)
{
    __shared__ float tile[32][33];
    const int j0 = blockIdx.x * 32, b0 = blockIdx.y * 32;
    for (int r = threadIdx.y; r < 32; r += 8) {
        int j = j0 + r, bb = b0 + threadIdx.x;
        tile[r][threadIdx.x] = (j < F) ? st[(size_t)j * B + bb] : 0.0f;
    }
    __syncthreads();
    for (int r = threadIdx.y; r < 32; r += 8) {
        int bb = b0 + r, j = j0 + threadIdx.x;
        if (j < F) out[(size_t)bb * F + j] = tile[threadIdx.x][r];
    }
}

// ---------------------------------------------------------------------------
extern "C" void kernel_launch(void* const* d_in, const int* in_sizes, int n_in,
                              void* d_out, int out_size)
{
    (void)in_sizes; (void)n_in; (void)out_size;
    const float* inputs = (const float*)d_in[0];
    const float* h[7];
    for (int i = 0; i < 7; i++) h[i] = (const float*)d_in[1 + i];
    const float* w1x = (const float*)d_in[8];  const float* b1x = (const float*)d_in[9];
    const float* w1r = (const float*)d_in[10]; const float* b1r = (const float*)d_in[11];
    const float* w1m = (const float*)d_in[12]; const float* b1m = (const float*)d_in[13];
    const float* w1a = (const float*)d_in[14]; const float* b1a = (const float*)d_in[15];
    const float* w2x = (const float*)d_in[16]; const float* b2x = (const float*)d_in[17];
    const float* w2r = (const float*)d_in[18]; const float* b2r = (const float*)d_in[19];
    const float* w2m = (const float*)d_in[20]; const float* b2m = (const float*)d_in[21];
    const float* w2a = (const float*)d_in[22]; const float* b2a = (const float*)d_in[23];
    const float* w3x = (const float*)d_in[24]; const float* b3x = (const float*)d_in[25];
    const float* w3m = (const float*)d_in[26]; const float* b3m = (const float*)d_in[27];
    float* out = (float*)d_out;

    float *XT, *ST, *M3, *D1, *D2, *D3;
    cudaGetSymbolAddress((void**)&XT, g_XT);
    cudaGetSymbolAddress((void**)&ST, g_state);
    cudaGetSymbolAddress((void**)&M3, g_m3);
    cudaGetSymbolAddress((void**)&D1, g_d1);
    cudaGetSymbolAddress((void**)&D2, g_d2);
    cudaGetSymbolAddress((void**)&D3, g_d3);

    const size_t HB = (size_t)H * B;
    #define STP(p, s) (ST + ((size_t)(p) * 6 + (s)) * HB)
    #define M3P(p)    (M3 + (size_t)(p) * O * B)

    dim3 tb(32, 8);
    // transpose inputs once per replay
    transpose_x_k<<<dim3(22, 4, T), tb>>>(inputs, XT);
    // initial states into parity 0 (h0..h5 -> 1024-wide states, h6 -> mem3)
    for (int s = 0; s < 6; s++)
        tr_in_k<<<dim3(32, 4), tb>>>(h[s], STP(0, s), H);
    tr_in_k<<<dim3(1, 4), tb>>>(h[6], M3P(0), O);

    for (int t = 0; t < T; t++) {
        const int p = t & 1, q = p ^ 1;
        // layer 1
        dense_k<<<128, 256>>>(XT + (size_t)t * DIN * B, w1x, DIN,
                              STP(p, SPK1), w1r, H, b1x, b1r, D1);
        tau_update_k<<<128, 256>>>(D1, STP(p, MEM1), STP(p, BB1), STP(p, SPK1),
                                   w1m, w1a, b1m, b1a,
                                   STP(q, MEM1), STP(q, SPK1), STP(q, BB1));
        // layer 2 (uses new spk1 and OLD spk1)
        dense_k<<<128, 256>>>(STP(q, SPK1), w2x, H,
                              STP(p, SPK1), w2r, H, b2x, b2r, D2);
        tau_update_k<<<128, 256>>>(D2, STP(p, MEM2), STP(p, BB2), STP(p, SPK2),
                                   w2m, w2a, b2m, b2a,
                                   STP(q, MEM2), STP(q, SPK2), STP(q, BB2));
        // output head
        out_gemm_k<<<20, 256>>>(STP(q, SPK2), w3x, b3x, D3);
        out_final_k<<<1, 128>>>(D3, M3P(p), w3m, b3m, M3P(q), out + (size_t)t * B * O);
    }

    // final states are in parity 0 (after t=99, new parity = 0)
    float* tail = out + (size_t)T * B * O;
    for (int s = 0; s < 6; s++)
        tr_out_k<<<dim3(32, 4), tb>>>(STP(0, s), tail + (size_t)s * HB, H);
    tr_out_k<<<dim3(1, 4), tb>>>(M3P(0), tail + 6 * HB, O);
}

// round 5
// speedup vs baseline: 5.7796x; 5.7796x over previous
#include <cuda_runtime.h>
#include <cuda_bf16.h>
#include <cstddef>

// ---------------------------------------------------------------------------
// SNN forward: ONE persistent kernel over all T=100 steps with software grid
// barriers. All inter-block data goes through L2 only (stcg/ldcg/cp.async.cg)
// because L1 is neither coherent nor flushed inside a single kernel.
// ---------------------------------------------------------------------------

#define B     128
#define T     100
#define DIN   700
#define DINP  704
#define H     1024
#define O     20
#define KT    16        // k-tile
#define NT    64        // neurons per block tile
#define NBLK  296       // persistent grid (148 SMs x 2, guaranteed resident)
#define SCALE 0.09999950000374997f   // 0.1 / sqrt(1 + 1e-5)

typedef unsigned long long ull;

// ---- device scratch ----
__device__ float g_XT[T * DINP * B];            // [t][i][b], rows 700..703 zero
__device__ float g_W1cat[H * (DINP + H)];       // [n][1728] = [w1x pad704 | w1r]
__device__ float g_W2cat[H * (2 * H)];          // [n][2048] = [w2x | w2r]
__device__ float g_state[12 * H * B];           // [parity][6][H*B]
__device__ float g_m3[2 * O * B];
__device__ float g_d1[H * B];
__device__ float g_d2[H * B];
__device__ float g_d3[O * B];
__device__ float g_part[18 * H * B];            // dense split-K partials
__device__ float g_partMA[16 * H * B];          // tau partials [m/a][8][H*B]
__device__ unsigned g_arrive;
__device__ unsigned g_phase;

enum { MEM1 = 0, SPK1, BB1, MEM2, SPK2, BB2 };

// ---- packed f32x2 helpers ----
__device__ __forceinline__ void fma2(ull& d, ull a, ull b) {
    asm("fma.rn.f32x2 %0, %1, %2, %0;" : "+l"(d) : "l"(a), "l"(b));
}
__device__ __forceinline__ ull dup2(float w) {
    ull r; asm("mov.b64 %0, {%1, %1};" : "=l"(r) : "f"(w)); return r;
}
__device__ __forceinline__ float2 unp2(ull v) {
    float2 r; asm("mov.b64 {%0, %1}, %2;" : "=f"(r.x), "=f"(r.y) : "l"(v)); return r;
}
__device__ __forceinline__ float sigmf(float x) { return 1.0f / (1.0f + expf(-x)); }

// ---- cp.async helpers (cg: L2-only, bypasses L1) ----
__device__ __forceinline__ void cpa16(float* dst_smem, const float* src) {
    unsigned d = (unsigned)__cvta_generic_to_shared(dst_smem);
    asm volatile("cp.async.cg.shared.global [%0], [%1], 16;\n" :: "r"(d), "l"(src));
}
__device__ __forceinline__ void cpa_commit() {
    asm volatile("cp.async.commit_group;\n" ::: "memory");
}
template<int N> __device__ __forceinline__ void cpa_wait() {
    asm volatile("cp.async.wait_group %0;\n" :: "n"(N) : "memory");
}

// ---- grid-wide barrier (sense via generation counter) ----
__device__ __forceinline__ void grid_bar(unsigned& gen) {
    __syncthreads();
    if (threadIdx.x == 0) {
        __threadfence();
        unsigned t = atomicAdd(&g_arrive, 1u);
        if (t == NBLK - 1) {
            *(volatile unsigned*)&g_arrive = 0u;
            __threadfence();
            atomicAdd(&g_phase, 1u);
        } else {
            volatile unsigned* ph = &g_phase;
            while (*ph == gen) { __nanosleep(64); }
            __threadfence();
        }
    }
    __syncthreads();
    gen++;
}

// ---------------------------------------------------------------------------
// Tiled GEMM job: partial[n0..n0+64][0..128] += A[k][b]*W[n][k] over k-tiles
// [tb,te). A from 2 concatenated segments, boundary at tiles_seg1*KT.
// 8 warps; warp owns 8 neurons; lane owns 4 batch rows. Smem 24KB dbl-buffered.
// ---------------------------------------------------------------------------
__device__ __forceinline__ void gemm_job(
    const float* __restrict__ Aseg1, const float* __restrict__ Aseg2,
    int tiles_seg1,
    const float* __restrict__ W, int Ktot,
    int tb, int te, int n0,
    float* __restrict__ partial,
    float* __restrict__ Abuf,      // [2][KT*B]
    float* __restrict__ Wbuf)      // [2][NT*KT]
{
    const int tid  = threadIdx.x;
    const int warp = tid >> 5, lane = tid & 31;
    const int seg1K = tiles_seg1 * KT;

    auto load_tile = [&](int tt, int buf) {
        const int kbase = tt * KT;
        const float* Ap = (tt < tiles_seg1) ? (Aseg1 + (size_t)kbase * B)
                                            : (Aseg2 + (size_t)(kbase - seg1K) * B);
        float* Ad = Abuf + buf * (KT * B);
        #pragma unroll
        for (int i = 0; i < 2; i++) {               // 512 float4, 2 per thread
            int f4 = tid + i * 256;
            cpa16(Ad + f4 * 4, Ap + f4 * 4);
        }
        float* Wd = Wbuf + buf * (NT * KT);
        {                                            // 256 float4, 1 per thread
            int f4 = tid;
            int j = f4 >> 2, c = f4 & 3;             // 4 float4 per 16-float row
            cpa16(Wd + j * KT + c * 4, W + (size_t)(n0 + j) * Ktot + kbase + c * 4);
        }
        cpa_commit();
    };

    ull acc[8][2];
    #pragma unroll
    for (int j = 0; j < 8; j++) { acc[j][0] = 0ull; acc[j][1] = 0ull; }

    const int nb = te - tb;
    load_tile(tb, 0);

    for (int t = 0; t < nb; t++) {
        const int buf = t & 1;
        if (t + 1 < nb) { load_tile(tb + t + 1, (t + 1) & 1); cpa_wait<1>(); }
        else            { cpa_wait<0>(); }
        __syncthreads();

        const float* As = Abuf + buf * (KT * B) + lane * 4;
        const float* Ws = Wbuf + buf * (NT * KT) + (warp * 8) * KT;
        #pragma unroll
        for (int kk = 0; kk < KT; kk += 4) {
            ulonglong2 a0 = *(const ulonglong2*)(As + (kk + 0) * B);
            ulonglong2 a1 = *(const ulonglong2*)(As + (kk + 1) * B);
            ulonglong2 a2 = *(const ulonglong2*)(As + (kk + 2) * B);
            ulonglong2 a3 = *(const ulonglong2*)(As + (kk + 3) * B);
            #pragma unroll
            for (int j = 0; j < 8; j++) {
                float4 w = *(const float4*)(Ws + j * KT + kk);
                ull w0 = dup2(w.x), w1 = dup2(w.y), w2 = dup2(w.z), w3 = dup2(w.w);
                fma2(acc[j][0], a0.x, w0); fma2(acc[j][1], a0.y, w0);
                fma2(acc[j][0], a1.x, w1); fma2(acc[j][1], a1.y, w1);
                fma2(acc[j][0], a2.x, w2); fma2(acc[j][1], a2.y, w2);
                fma2(acc[j][0], a3.x, w3); fma2(acc[j][1], a3.y, w3);
            }
        }
        __syncthreads();
    }

    float* outp = partial + (size_t)(n0 + warp * 8) * B + lane * 4;
    #pragma unroll
    for (int j = 0; j < 8; j++) {
        float2 lo = unp2(acc[j][0]), hi = unp2(acc[j][1]);
        __stcg((float4*)(outp + j * B), make_float4(lo.x, lo.y, hi.x, hi.y));
    }
}

// ---------------------------------------------------------------------------
// The persistent kernel: all 100 timesteps.
// ---------------------------------------------------------------------------
__global__ __launch_bounds__(256, 2) void snn_persist_k(
    const float* __restrict__ XT,
    const float* __restrict__ W1C, const float* __restrict__ W2C,
    const float* __restrict__ b1x, const float* __restrict__ b1r,
    const float* __restrict__ w1m, const float* __restrict__ b1m,
    const float* __restrict__ w1a, const float* __restrict__ b1a,
    const float* __restrict__ b2x, const float* __restrict__ b2r,
    const float* __restrict__ w2m, const float* __restrict__ b2m,
    const float* __restrict__ w2a, const float* __restrict__ b2a,
    const float* __restrict__ w3x, const float* __restrict__ b3x,
    const float* __restrict__ w3m, const float* __restrict__ b3m,
    float* __restrict__ ST, float* __restrict__ M3,
    float* __restrict__ D1, float* __restrict__ D2, float* __restrict__ D3,
    float* __restrict__ PART, float* __restrict__ PARTMA,
    float* __restrict__ out)
{
    __shared__ float smem[2 * KT * B + 2 * NT * KT];   // 24 KB
    float* Abuf = smem;
    float* Wbuf = smem + 2 * KT * B;

    const int bid = blockIdx.x;
    const int tid = threadIdx.x;
    const size_t HB = (size_t)H * B;
    unsigned gen = 0;

    #define STQ(p, s) (ST + ((size_t)(p) * 6 + (s)) * HB)

    for (int t = 0; t < T; t++) {
        const int p = t & 1, q = p ^ 1;

        // ---- P1: dense1 partials (K=1728 = 108 tiles, 18 splits x 16 ntiles) ----
        if (bid < 288) {
            const int nt = bid & 15, s = bid >> 4;
            gemm_job(XT + (size_t)t * DINP * B, STQ(p, SPK1), 44, W1C, DINP + H,
                     s * 6, s * 6 + 6, nt * NT, PART + (size_t)s * HB, Abuf, Wbuf);
        }
        grid_bar(gen);

        // ---- P2: reduce D1 ----
        {
            const int idx = bid * 256 + tid;
            if (idx < (int)(HB / 4)) {
                const size_t off = (size_t)idx * 4;
                float4 s4 = make_float4(0.f, 0.f, 0.f, 0.f);
                for (int k = 0; k < 18; k++) {
                    float4 pp = __ldcg((const float4*)(PART + (size_t)k * HB + off));
                    s4.x += pp.x; s4.y += pp.y; s4.z += pp.z; s4.w += pp.w;
                }
                const int n = (int)(off >> 7);
                const float bb = b1x[n] + b1r[n];
                __stcg((float4*)(D1 + off),
                       make_float4(SCALE * (s4.x + bb), SCALE * (s4.y + bb),
                                   SCALE * (s4.z + bb), SCALE * (s4.w + bb)));
            }
        }
        grid_bar(gen);

        // ---- P3: tau1 partials (K=2048 = 128 tiles; 16nt x 8s x 2z) ----
        if (bid < 256) {
            const int nt = bid & 15, s = (bid >> 4) & 7, z = bid >> 7;
            gemm_job(D1, z ? STQ(p, BB1) : STQ(p, MEM1), 64,
                     z ? w1a : w1m, 2 * H, s * 16, s * 16 + 16, nt * NT,
                     PARTMA + (size_t)(z * 8 + s) * HB, Abuf, Wbuf);
        }
        grid_bar(gen);

        // ---- P4: tau1 reduce + adaptive update -> parity q ----
        {
            const int idx = bid * 256 + tid;
            if (idx < (int)(HB / 4)) {
                const size_t off = (size_t)idx * 4;
                float4 sm = make_float4(0.f, 0.f, 0.f, 0.f);
                float4 sa = make_float4(0.f, 0.f, 0.f, 0.f);
                for (int k = 0; k < 8; k++) {
                    float4 pm = __ldcg((const float4*)(PARTMA + (size_t)k * HB + off));
                    float4 pa = __ldcg((const float4*)(PARTMA + (size_t)(8 + k) * HB + off));
                    sm.x += pm.x; sm.y += pm.y; sm.z += pm.z; sm.w += pm.w;
                    sa.x += pa.x; sa.y += pa.y; sa.z += pa.z; sa.w += pa.w;
                }
                const int n = (int)(off >> 7);
                const float bmo = b1m[n], bao = b1a[n];
                float4 dn = __ldcg((const float4*)(D1 + off));
                float4 me = __ldcg((const float4*)(STQ(p, MEM1) + off));
                float4 bo = __ldcg((const float4*)(STQ(p, BB1) + off));
                float4 sp = __ldcg((const float4*)(STQ(p, SPK1) + off));
                float tmv[4] = { sigmf(sm.x+bmo), sigmf(sm.y+bmo), sigmf(sm.z+bmo), sigmf(sm.w+bmo) };
                float tav[4] = { sigmf(sa.x+bao), sigmf(sa.y+bao), sigmf(sa.z+bao), sigmf(sa.w+bao) };
                float dv[4] = { dn.x, dn.y, dn.z, dn.w };
                float mv[4] = { me.x, me.y, me.z, me.w };
                float bv[4] = { bo.x, bo.y, bo.z, bo.w };
                float sv[4] = { sp.x, sp.y, sp.z, sp.w };
                float nm[4], ns[4], nb[4];
                #pragma unroll
                for (int j = 0; j < 4; j++) {
                    float bn  = tav[j] * bv[j] + (1.0f - tav[j]) * sv[j];
                    float Bth = 0.1f + 1.8f * bn;
                    float mn  = mv[j] + (dv[j] - mv[j]) * tmv[j];
                    float s   = (mn - Bth) > 0.0f ? 1.0f : 0.0f;
                    nm[j] = (1.0f - s) * mn; ns[j] = s; nb[j] = bn;
                }
                __stcg((float4*)(STQ(q, MEM1) + off), make_float4(nm[0], nm[1], nm[2], nm[3]));
                __stcg((float4*)(STQ(q, SPK1) + off), make_float4(ns[0], ns[1], ns[2], ns[3]));
                __stcg((float4*)(STQ(q, BB1)  + off), make_float4(nb[0], nb[1], nb[2], nb[3]));
            }
        }
        grid_bar(gen);

        // ---- P5: dense2 partials (K=2048=128 tiles, 18 splits) ----
        if (bid < 288) {
            const int nt = bid & 15, s = bid >> 4;
            const int tbgn = (128 * s) / 18, tend = (128 * (s + 1)) / 18;
            gemm_job(STQ(q, SPK1), STQ(p, SPK1), 64, W2C, 2 * H,
                     tbgn, tend, nt * NT, PART + (size_t)s * HB, Abuf, Wbuf);
        }
        grid_bar(gen);

        // ---- P6: reduce D2 ----
        {
            const int idx = bid * 256 + tid;
            if (idx < (int)(HB / 4)) {
                const size_t off = (size_t)idx * 4;
                float4 s4 = make_float4(0.f, 0.f, 0.f, 0.f);
                for (int k = 0; k < 18; k++) {
                    float4 pp = __ldcg((const float4*)(PART + (size_t)k * HB + off));
                    s4.x += pp.x; s4.y += pp.y; s4.z += pp.z; s4.w += pp.w;
                }
                const int n = (int)(off >> 7);
                const float bb = b2x[n] + b2r[n];
                __stcg((float4*)(D2 + off),
                       make_float4(SCALE * (s4.x + bb), SCALE * (s4.y + bb),
                                   SCALE * (s4.z + bb), SCALE * (s4.w + bb)));
            }
        }
        grid_bar(gen);

        // ---- P7: tau2 partials ----
        if (bid < 256) {
            const int nt = bid & 15, s = (bid >> 4) & 7, z = bid >> 7;
            gemm_job(D2, z ? STQ(p, BB2) : STQ(p, MEM2), 64,
                     z ? w2a : w2m, 2 * H, s * 16, s * 16 + 16, nt * NT,
                     PARTMA + (size_t)(z * 8 + s) * HB, Abuf, Wbuf);
        }
        grid_bar(gen);

        // ---- P8: tau2 reduce + update -> parity q ----
        {
            const int idx = bid * 256 + tid;
            if (idx < (int)(HB / 4)) {
                const size_t off = (size_t)idx * 4;
                float4 sm = make_float4(0.f, 0.f, 0.f, 0.f);
                float4 sa = make_float4(0.f, 0.f, 0.f, 0.f);
                for (int k = 0; k < 8; k++) {
                    float4 pm = __ldcg((const float4*)(PARTMA + (size_t)k * HB + off));
                    float4 pa = __ldcg((const float4*)(PARTMA + (size_t)(8 + k) * HB + off));
                    sm.x += pm.x; sm.y += pm.y; sm.z += pm.z; sm.w += pm.w;
                    sa.x += pa.x; sa.y += pa.y; sa.z += pa.z; sa.w += pa.w;
                }
                const int n = (int)(off >> 7);
                const float bmo = b2m[n], bao = b2a[n];
                float4 dn = __ldcg((const float4*)(D2 + off));
                float4 me = __ldcg((const float4*)(STQ(p, MEM2) + off));
                float4 bo = __ldcg((const float4*)(STQ(p, BB2) + off));
                float4 sp = __ldcg((const float4*)(STQ(p, SPK2) + off));
                float tmv[4] = { sigmf(sm.x+bmo), sigmf(sm.y+bmo), sigmf(sm.z+bmo), sigmf(sm.w+bmo) };
                float tav[4] = { sigmf(sa.x+bao), sigmf(sa.y+bao), sigmf(sa.z+bao), sigmf(sa.w+bao) };
                float dv[4] = { dn.x, dn.y, dn.z, dn.w };
                float mv[4] = { me.x, me.y, me.z, me.w };
                float bv[4] = { bo.x, bo.y, bo.z, bo.w };
                float sv[4] = { sp.x, sp.y, sp.z, sp.w };
                float nm[4], ns[4], nb[4];
                #pragma unroll
                for (int j = 0; j < 4; j++) {
                    float bn  = tav[j] * bv[j] + (1.0f - tav[j]) * sv[j];
                    float Bth = 0.1f + 1.8f * bn;
                    float mn  = mv[j] + (dv[j] - mv[j]) * tmv[j];
                    float s   = (mn - Bth) > 0.0f ? 1.0f : 0.0f;
                    nm[j] = (1.0f - s) * mn; ns[j] = s; nb[j] = bn;
                }
                __stcg((float4*)(STQ(q, MEM2) + off), make_float4(nm[0], nm[1], nm[2], nm[3]));
                __stcg((float4*)(STQ(q, SPK2) + off), make_float4(ns[0], ns[1], ns[2], ns[3]));
                __stcg((float4*)(STQ(q, BB2)  + off), make_float4(nb[0], nb[1], nb[2], nb[3]));
            }
        }
        grid_bar(gen);

        // ---- P9a: head GEMM, 20 blocks (class = bid), K=1024 ----
        if (bid < 20) {
            const int warp = tid >> 5, lane = tid & 31;
            const int o = bid;
            const float* A = STQ(q, SPK2) + (size_t)(warp * 128) * B + lane * 4;
            const float* Wr = w3x + (size_t)o * H + warp * 128;
            float a0 = 0.f, a1 = 0.f, a2 = 0.f, a3 = 0.f;
            #pragma unroll 4
            for (int k = 0; k < 128; k++) {
                float4 av = __ldcg((const float4*)(A + (size_t)k * B));
                float wv = Wr[k];
                a0 += av.x * wv; a1 += av.y * wv; a2 += av.z * wv; a3 += av.w * wv;
            }
            float* red = smem;              // [8][128] scratch (4 KB)
            red[warp * B + lane * 4 + 0] = a0;
            red[warp * B + lane * 4 + 1] = a1;
            red[warp * B + lane * 4 + 2] = a2;
            red[warp * B + lane * 4 + 3] = a3;
            __syncthreads();
            if (tid < B) {
                float s = 0.f;
                #pragma unroll
                for (int w = 0; w < 8; w++) s += red[w * B + tid];
                __stcg(D3 + o * B + tid, SCALE * (s + b3x[o]));
            }
            __syncthreads();
        }
        grid_bar(gen);

        // ---- P9b: final blend + log-softmax (block 0 only; no barrier,
        //      covered by next step's P1 barrier) ----
        if (bid == 0 && tid < B) {
            const int b = tid;
            float d3v[O], m3v[O], nm[O];
            #pragma unroll
            for (int k = 0; k < O; k++) {
                d3v[k] = __ldcg(D3 + k * B + b);
                m3v[k] = __ldcg(M3 + (size_t)p * O * B + k * B + b);
            }
            #pragma unroll
            for (int o = 0; o < O; o++) {
                const float* w = w3m + o * (2 * O);
                float acc = b3m[o];
                #pragma unroll
                for (int k = 0; k < O; k++) acc += d3v[k] * w[k];
                #pragma unroll
                for (int k = 0; k < O; k++) acc += m3v[k] * w[O + k];
                float tm = sigmf(acc);
                float v = (1.0f - tm) * m3v[o] + d3v[o] * tm;
                nm[o] = v;
                __stcg(M3 + (size_t)q * O * B + o * B + b, v);
            }
            float mx = nm[0];
            #pragma unroll
            for (int o = 1; o < O; o++) mx = fmaxf(mx, nm[o]);
            float s = 0.f;
            #pragma unroll
            for (int o = 0; o < O; o++) s += expf(nm[o] - mx);
            float lse = logf(s);
            #pragma unroll
            for (int o = 0; o < O; o++) out[(size_t)t * B * O + b * O + o] = nm[o] - mx - lse;
        }
    }
    #undef STQ
}

// ---------------------------------------------------------------------------
// Pre/post kernels
// ---------------------------------------------------------------------------
__global__ void init_bar_k() {
    if (threadIdx.x == 0) { g_arrive = 0u; g_phase = 0u; }
}

__global__ void transpose_x_k(const float* __restrict__ in, float* __restrict__ out)
{
    __shared__ float tile[32][33];
    const int t = blockIdx.z;
    const int i0 = blockIdx.x * 32, b0 = blockIdx.y * 32;
    for (int r = threadIdx.y; r < 32; r += 8) {
        int bb = b0 + r, i = i0 + threadIdx.x;
        tile[r][threadIdx.x] = (i < DIN) ? in[(size_t)bb * T * DIN + (size_t)t * DIN + i] : 0.0f;
    }
    __syncthreads();
    for (int r = threadIdx.y; r < 32; r += 8) {
        int i = i0 + r, bb = b0 + threadIdx.x;
        out[((size_t)t * DINP + i) * B + bb] = tile[threadIdx.x][r];
    }
}

__global__ void tr_in_k(const float* __restrict__ in, float* __restrict__ st, int F)
{
    __shared__ float tile[32][33];
    const int j0 = blockIdx.x * 32, b0 = blockIdx.y * 32;
    for (int r = threadIdx.y; r < 32; r += 8) {
        int bb = b0 + r, j = j0 + threadIdx.x;
        tile[r][threadIdx.x] = (j < F) ? in[(size_t)bb * F + j] : 0.0f;
    }
    __syncthreads();
    for (int r = threadIdx.y; r < 32; r += 8) {
        int j = j0 + r, bb = b0 + threadIdx.x;
        if (j < F) st[(size_t)j * B + bb] = tile[threadIdx.x][r];
    }
}

__global__ void tr_out_k(const float* __restrict__ st, float* __restrict__ out, int F)
{
    __shared__ float tile[32][33];
    const int j0 = blockIdx.x * 32, b0 = blockIdx.y * 32;
    for (int r = threadIdx.y; r < 32; r += 8) {
        int j = j0 + r, bb = b0 + threadIdx.x;
        tile[r][threadIdx.x] = (j < F) ? st[(size_t)j * B + bb] : 0.0f;
    }
    __syncthreads();
    for (int r = threadIdx.y; r < 32; r += 8) {
        int bb = b0 + r, j = j0 + threadIdx.x;
        if (j < F) out[(size_t)bb * F + j] = tile[threadIdx.x][r];
    }
}

__global__ void catW1_k(const float* __restrict__ w1x, const float* __restrict__ w1r,
                        float* __restrict__ Wcat)
{
    int idx = blockIdx.x * 256 + threadIdx.x;
    if (idx >= H * (DINP + H)) return;
    int n = idx / (DINP + H), c = idx % (DINP + H);
    float v;
    if (c < DINP) v = (c < DIN) ? w1x[(size_t)n * DIN + c] : 0.0f;
    else          v = w1r[(size_t)n * H + (c - DINP)];
    Wcat[idx] = v;
}

__global__ void catW2_k(const float* __restrict__ w2x, const float* __restrict__ w2r,
                        float* __restrict__ Wcat)
{
    int idx = blockIdx.x * 256 + threadIdx.x;
    if (idx >= H * 2 * H) return;
    int n = idx / (2 * H), c = idx % (2 * H);
    Wcat[idx] = (c < H) ? w2x[(size_t)n * H + c] : w2r[(size_t)n * H + (c - H)];
}

// ---------------------------------------------------------------------------
extern "C" void kernel_launch(void* const* d_in, const int* in_sizes, int n_in,
                              void* d_out, int out_size)
{
    (void)in_sizes; (void)n_in; (void)out_size;
    const float* inputs = (const float*)d_in[0];
    const float* h[7];
    for (int i = 0; i < 7; i++) h[i] = (const float*)d_in[1 + i];
    const float* w1x = (const float*)d_in[8];  const float* b1x = (const float*)d_in[9];
    const float* w1r = (const float*)d_in[10]; const float* b1r = (const float*)d_in[11];
    const float* w1m = (const float*)d_in[12]; const float* b1m = (const float*)d_in[13];
    const float* w1a = (const float*)d_in[14]; const float* b1a = (const float*)d_in[15];
    const float* w2x = (const float*)d_in[16]; const float* b2x = (const float*)d_in[17];
    const float* w2r = (const float*)d_in[18]; const float* b2r = (const float*)d_in[19];
    const float* w2m = (const float*)d_in[20]; const float* b2m = (const float*)d_in[21];
    const float* w2a = (const float*)d_in[22]; const float* b2a = (const float*)d_in[23];
    const float* w3x = (const float*)d_in[24]; const float* b3x = (const float*)d_in[25];
    const float* w3m = (const float*)d_in[26]; const float* b3m = (const float*)d_in[27];
    float* out = (float*)d_out;

    float *XT, *ST, *M3, *D1, *D2, *D3, *PART, *PARTMA, *W1C, *W2C;
    cudaGetSymbolAddress((void**)&XT, g_XT);
    cudaGetSymbolAddress((void**)&ST, g_state);
    cudaGetSymbolAddress((void**)&M3, g_m3);
    cudaGetSymbolAddress((void**)&D1, g_d1);
    cudaGetSymbolAddress((void**)&D2, g_d2);
    cudaGetSymbolAddress((void**)&D3, g_d3);
    cudaGetSymbolAddress((void**)&PART, g_part);
    cudaGetSymbolAddress((void**)&PARTMA, g_partMA);
    cudaGetSymbolAddress((void**)&W1C, g_W1cat);
    cudaGetSymbolAddress((void**)&W2C, g_W2cat);

    const size_t HB = (size_t)H * B;
    #define STP(p, s) (ST + ((size_t)(p) * 6 + (s)) * HB)

    dim3 tb(32, 8);
    transpose_x_k<<<dim3(22, 4, T), tb>>>(inputs, XT);
    catW1_k<<<(H * (DINP + H) + 255) / 256, 256>>>(w1x, w1r, W1C);
    catW2_k<<<(H * 2 * H + 255) / 256, 256>>>(w2x, w2r, W2C);
    for (int s = 0; s < 6; s++)
        tr_in_k<<<dim3(32, 4), tb>>>(h[s], STP(0, s), H);
    tr_in_k<<<dim3(1, 4), tb>>>(h[6], M3, O);
    init_bar_k<<<1, 32>>>();

    snn_persist_k<<<NBLK, 256>>>(
        XT, W1C, W2C,
        b1x, b1r, w1m, b1m, w1a, b1a,
        b2x, b2r, w2m, b2m, w2a, b2a,
        w3x, b3x, w3m, b3m,
        ST, M3, D1, D2, D3, PART, PARTMA, out);

    float* tail = out + (size_t)T * B * O;
    for (int s = 0; s < 6; s++)
        tr_out_k<<<dim3(32, 4), tb>>>(STP(0, s), tail + (size_t)s * HB, H);
    tr_out_k<<<dim3(1, 4), tb>>>(M3, tail + 6 * HB, O);
}